// round 1
// baseline (speedup 1.0000x reference)
#include <cuda_runtime.h>
#include <cuda_bf16.h>
#include <math.h>

// HSIC_1855425872455: X [2048,16] fp32 -> scalar fp32
// Pipeline:
//  k1 hsic_stats : column sums -> per-feature scale s_c = sqrt(log2e/(2*meanD_c)); zero g_T
//  k1b hsic_scale: g_Xs = X * s_c   (so inner loop is k = 2^(-(u-v)^2))
//  k2 hsic_main  : per block (2 rows): A row sums + strict-upper-tri T outer product
//  k3 hsic_dm    : Dm[a,b] = sum_i (A_a[i]-1)(A_b[i]-1)  (fp64), S_c = sum_i (A_c[i]-1)
//  k4 hsic_final : combine in fp64, sum hsic^2 over i<j, write fp32 scalar

#define N 2048
#define F 16
#define NPAIR 120        // strict upper triangle of 16x16
#define ROWS_PER_BLOCK 2
#define TRI(a,b) ((a)*15 - (a)*((a)-1)/2 + ((b)-(a)-1))

__device__ float  g_scale[F];
__device__ float  g_Xs[N * F];
__device__ float  g_A[N * F];
__device__ double g_T[NPAIR];
__device__ double g_Dm[NPAIR];
__device__ double g_S[F];

__device__ __forceinline__ float wred(float v) {
    v += __shfl_xor_sync(0xffffffffu, v, 16);
    v += __shfl_xor_sync(0xffffffffu, v, 8);
    v += __shfl_xor_sync(0xffffffffu, v, 4);
    v += __shfl_xor_sync(0xffffffffu, v, 2);
    v += __shfl_xor_sync(0xffffffffu, v, 1);
    return v;
}

// ---------------------------------------------------------------------------
// k1: column mean / mean-of-squares -> scale; also zero the T accumulators.
// meanD_c = 2*(m2 - m1^2); K = exp(-D/(2*meanD)); fold log2(e) into the scale:
// Xs = X * sqrt(log2e/(2*meanD))  =>  k = exp2(-(xi_s - xj_s)^2)
// ---------------------------------------------------------------------------
__global__ void hsic_stats(const float* __restrict__ X) {
    const int tid = threadIdx.x;          // 256 threads, 1 block
    const int col = tid & 15, part = tid >> 4;   // 16 partials per column
    double s = 0.0, sq = 0.0;
    for (int r = part; r < N; r += 16) {
        float v = X[r * F + col];
        s += (double)v;
        sq += (double)v * (double)v;
    }
    __shared__ double sh_s[256], sh_q[256];
    sh_s[tid] = s; sh_q[tid] = sq;
    __syncthreads();
    if (tid < F) {
        double ts = 0.0, tq = 0.0;
        #pragma unroll
        for (int p = 0; p < 16; p++) { ts += sh_s[p * 16 + tid]; tq += sh_q[p * 16 + tid]; }
        double m1 = ts / (double)N, m2 = tq / (double)N;
        double meanD = 2.0 * (m2 - m1 * m1);
        double sc = sqrt(1.4426950408889634 / (2.0 * meanD));
        g_scale[tid] = (float)sc;
    }
    if (tid < NPAIR) g_T[tid] = 0.0;
}

__global__ void hsic_scale(const float* __restrict__ X) {
    int idx = blockIdx.x * blockDim.x + threadIdx.x;
    if (idx < N * F) g_Xs[idx] = X[idx] * g_scale[idx & 15];
}

// ---------------------------------------------------------------------------
// k2: main pass. Block owns ROWS_PER_BLOCK rows i; each thread sweeps j strided.
// Accumulates (unmasked) A_raw[i][c] = sum_j k_c(i,j)  and
// T_raw[a][b] = sum_{i in block} sum_j k_a k_b  (strict upper tri).
// Diagonal (j==i, k==1) is corrected analytically downstream (A-1, T-n).
// ---------------------------------------------------------------------------
__global__ __launch_bounds__(256, 1) void hsic_main() {
    const int tid  = threadIdx.x;
    const int warp = tid >> 5, lane = tid & 31;
    __shared__ float s_xi[F];
    __shared__ float s_t[8 * NPAIR];
    __shared__ float s_a[8 * F];

    float t[NPAIR];
    #pragma unroll
    for (int e = 0; e < NPAIR; e++) t[e] = 0.f;

    for (int rr = 0; rr < ROWS_PER_BLOCK; rr++) {
        const int i = blockIdx.x * ROWS_PER_BLOCK + rr;
        if (tid < F) s_xi[tid] = g_Xs[i * F + tid];
        __syncthreads();
        float xi[F];
        #pragma unroll
        for (int c = 0; c < F; c++) xi[c] = s_xi[c];
        float a[F];
        #pragma unroll
        for (int c = 0; c < F; c++) a[c] = 0.f;

        for (int j = tid; j < N; j += 256) {
            const float4* p = (const float4*)(g_Xs + j * F);
            float4 v0 = p[0], v1 = p[1], v2 = p[2], v3 = p[3];
            float xj[F] = {v0.x, v0.y, v0.z, v0.w, v1.x, v1.y, v1.z, v1.w,
                           v2.x, v2.y, v2.z, v2.w, v3.x, v3.y, v3.z, v3.w};
            float k[F];
            #pragma unroll
            for (int c = 0; c < F; c++) {
                float d = xi[c] - xj[c];
                float arg = -d * d;
                float kk;
                asm("ex2.approx.f32 %0, %1;" : "=f"(kk) : "f"(arg));
                k[c] = kk;
                a[c] += kk;
            }
            #pragma unroll
            for (int c1 = 0; c1 < F; c1++)
                #pragma unroll
                for (int c2 = c1 + 1; c2 < F; c2++)
                    t[TRI(c1, c2)] += k[c1] * k[c2];
        }

        // reduce row sums A for this row
        #pragma unroll
        for (int c = 0; c < F; c++) a[c] = wred(a[c]);
        if (lane == 0) {
            #pragma unroll
            for (int c = 0; c < F; c++) s_a[warp * F + c] = a[c];
        }
        __syncthreads();
        if (tid < F) {
            float s = 0.f;
            #pragma unroll
            for (int w = 0; w < 8; w++) s += s_a[w * F + tid];
            g_A[i * F + tid] = s;
        }
        __syncthreads();
    }

    // reduce T partials: warp shuffle -> smem -> fp64 atomic
    #pragma unroll
    for (int e = 0; e < NPAIR; e++) t[e] = wred(t[e]);
    if (lane == 0) {
        #pragma unroll
        for (int e = 0; e < NPAIR; e++) s_t[warp * NPAIR + e] = t[e];
    }
    __syncthreads();
    for (int e = tid; e < NPAIR; e += 256) {
        double s = 0.0;
        #pragma unroll
        for (int w = 0; w < 8; w++) s += (double)s_t[w * NPAIR + e];
        atomicAdd(&g_T[e], s);
    }
}

// ---------------------------------------------------------------------------
// k3: blocks 0..119 -> Dm entries (fp64); block 120 -> S (fp64). A corrected by -1.
// ---------------------------------------------------------------------------
__global__ void hsic_dm() {
    const int e = blockIdx.x;
    const int tid = threadIdx.x;
    __shared__ double sh[256];
    if (e < NPAIR) {
        int aa = 0, rem = e;
        while (rem >= 15 - aa) { rem -= 15 - aa; aa++; }
        int bb = aa + 1 + rem;
        double acc = 0.0;
        for (int i = tid; i < N; i += 256) {
            double fa = (double)g_A[i * F + aa] - 1.0;
            double fb = (double)g_A[i * F + bb] - 1.0;
            acc += fa * fb;
        }
        sh[tid] = acc;
        __syncthreads();
        for (int off = 128; off > 0; off >>= 1) {
            if (tid < off) sh[tid] += sh[tid + off];
            __syncthreads();
        }
        if (tid == 0) g_Dm[e] = sh[0];
    } else {
        const int col = tid & 15, part = tid >> 4;
        double acc = 0.0;
        for (int r = part; r < N; r += 16) acc += (double)g_A[r * F + col] - 1.0;
        sh[tid] = acc;
        __syncthreads();
        if (tid < F) {
            double s = 0.0;
            #pragma unroll
            for (int p = 0; p < 16; p++) s += sh[p * 16 + tid];
            g_S[tid] = s;
        }
    }
}

// ---------------------------------------------------------------------------
// k4: combine in fp64, sum hsic^2 over strict upper triangle, write fp32.
// ---------------------------------------------------------------------------
__global__ void hsic_final(float* __restrict__ out) {
    __shared__ double sh[128];
    const int tid = threadIdx.x;
    double v = 0.0;
    if (tid < NPAIR) {
        int aa = 0, rem = tid;
        while (rem >= 15 - aa) { rem -= 15 - aa; aa++; }
        int bb = aa + 1 + rem;
        const double n = (double)N;
        double T = g_T[tid] - n;                       // remove diagonal contribution
        double c0 = 1.0 / (n * (n - 3.0));
        double h = c0 * (T + g_S[aa] * g_S[bb] / ((n - 1.0) * (n - 2.0))
                           - (2.0 / (n - 2.0)) * g_Dm[tid]);
        v = h * h;
    }
    sh[tid] = v;
    __syncthreads();
    for (int off = 64; off > 0; off >>= 1) {
        if (tid < off) sh[tid] += sh[tid + off];
        __syncthreads();
    }
    if (tid == 0) out[0] = (float)sh[0];
}

extern "C" void kernel_launch(void* const* d_in, const int* in_sizes, int n_in,
                              void* d_out, int out_size) {
    const float* X = (const float*)d_in[0];
    hsic_stats<<<1, 256>>>(X);
    hsic_scale<<<(N * F + 255) / 256, 256>>>(X);
    hsic_main<<<N / ROWS_PER_BLOCK, 256>>>();
    hsic_dm<<<NPAIR + 1, 256>>>();
    hsic_final<<<1, 128>>>((float*)d_out);
}

// round 2
// speedup vs baseline: 1.0663x; 1.0663x over previous
#include <cuda_runtime.h>
#include <cuda_bf16.h>
#include <math.h>

// HSIC_1855425872455: X [2048,16] fp32 -> scalar fp32
// R2: packed f32x2 outer product, packed (c,c+8) feature layout, fast small kernels.

#define N 2048
#define F 16
#define NPAIR 120
#define ROWS_PER_BLOCK 2
#define TRI16(a,b) ((a)*15 - (a)*((a)-1)/2 + ((b)-(a)-1))
#define TRI8(a,b)  ((a)*7  - (a)*((a)-1)/2 + ((b)-(a)-1))

typedef unsigned long long u64;

__device__ float  g_scale[F];
__device__ float  g_Xs[N * F];     // packed layout: row j = 8 float2 pairs (c, c+8)
__device__ float  g_A[N * F];      // canonical layout
__device__ double g_T[NPAIR];
__device__ double g_Dm[NPAIR];
__device__ double g_S[F];

// ---- f32x2 helpers -------------------------------------------------------
__device__ __forceinline__ u64 pk(float lo, float hi) {
    u64 r; asm("mov.b64 %0, {%1, %2};" : "=l"(r) : "f"(lo), "f"(hi)); return r;
}
__device__ __forceinline__ void upk(u64 v, float& lo, float& hi) {
    asm("mov.b64 {%0, %1}, %2;" : "=f"(lo), "=f"(hi) : "l"(v));
}
__device__ __forceinline__ u64 fma2(u64 a, u64 b, u64 c) {
    u64 r; asm("fma.rn.f32x2 %0, %1, %2, %3;" : "=l"(r) : "l"(a), "l"(b), "l"(c)); return r;
}
__device__ __forceinline__ u64 add2(u64 a, u64 b) {
    u64 r; asm("add.rn.f32x2 %0, %1, %2;" : "=l"(r) : "l"(a), "l"(b)); return r;
}
__device__ __forceinline__ float wred(float v) {
    v += __shfl_xor_sync(0xffffffffu, v, 16);
    v += __shfl_xor_sync(0xffffffffu, v, 8);
    v += __shfl_xor_sync(0xffffffffu, v, 4);
    v += __shfl_xor_sync(0xffffffffu, v, 2);
    v += __shfl_xor_sync(0xffffffffu, v, 1);
    return v;
}

// ---------------------------------------------------------------------------
// k1: column stats -> scale; zero accumulators. 1 block, 1024 threads.
// fp32 per-thread partials (32 elems each), fp64 cross-thread reduce.
// ---------------------------------------------------------------------------
__global__ void hsic_stats(const float* __restrict__ X) {
    const int tid = threadIdx.x;
    const int col = tid & 15, part = tid >> 4;     // 64 partials per column
    float s = 0.f, sq = 0.f;
    for (int r = part; r < N; r += 64) {
        float v = X[r * F + col];
        s += v;
        sq = fmaf(v, v, sq);
    }
    __shared__ float shs[1024], shq[1024];
    shs[tid] = s; shq[tid] = sq;
    __syncthreads();
    if (tid < F) {
        double ts = 0.0, tq = 0.0;
        #pragma unroll
        for (int p = 0; p < 64; p++) { ts += (double)shs[p * 16 + tid]; tq += (double)shq[p * 16 + tid]; }
        double m1 = ts / (double)N, m2 = tq / (double)N;
        double meanD = 2.0 * (m2 - m1 * m1);
        g_scale[tid] = (float)sqrt(1.4426950408889634 / (2.0 * meanD));
    }
    if (tid < NPAIR) { g_T[tid] = 0.0; g_Dm[tid] = 0.0; }
    if (tid < F) g_S[tid] = 0.0;
}

// ---------------------------------------------------------------------------
// k1b: scale + repack into (c, c+8) interleaved layout.
// feature c -> slot 2*(c&7) + (c>>3) within the 16-float row.
// ---------------------------------------------------------------------------
__global__ void hsic_scale(const float* __restrict__ X) {
    int idx = blockIdx.x * blockDim.x + threadIdx.x;
    if (idx < N * F) {
        int row = idx >> 4, c = idx & 15;
        int pos = row * F + ((c & 7) * 2 + (c >> 3));
        g_Xs[pos] = X[idx] * g_scale[c];
    }
}

// ---------------------------------------------------------------------------
// k2: main pass with packed f32x2 outer product.
// tLL[i<j]  lane0 = T[i][j],     lane1 = T[i+8][j+8]
// tX [i<j]  lane0 = T[i][j+8],   lane1 = T[j][i+8]
// tD [i]    = T[i][i+8]
// Diagonal (j==i) contributes k=1 everywhere; corrected downstream (A-1, T-n).
// ---------------------------------------------------------------------------
__global__ __launch_bounds__(256) void hsic_main() {
    const int tid  = threadIdx.x;
    const int warp = tid >> 5, lane = tid & 31;
    __shared__ float s_t[8 * NPAIR];
    __shared__ float s_a[8 * F];

    u64 tLL[28], tX[28];
    float tD[8];
    #pragma unroll
    for (int e = 0; e < 28; e++) { tLL[e] = 0ull; tX[e] = 0ull; }
    #pragma unroll
    for (int e = 0; e < 8; e++) tD[e] = 0.f;

    for (int rr = 0; rr < ROWS_PER_BLOCK; rr++) {
        const int i = blockIdx.x * ROWS_PER_BLOCK + rr;
        // load row i (packed layout), negate: all threads load same 64B -> L1 broadcast
        const u64* xrow = (const u64*)(g_Xs + i * F);
        u64 nxi[8];
        #pragma unroll
        for (int c = 0; c < 8; c++) {
            float lo, hi; upk(xrow[c], lo, hi);
            nxi[c] = pk(-lo, -hi);
        }
        u64 a_p[8];
        #pragma unroll
        for (int c = 0; c < 8; c++) a_p[c] = 0ull;

        for (int j = tid; j < N; j += 256) {
            const ulonglong2* pj = (const ulonglong2*)(g_Xs + j * F);
            ulonglong2 w0 = pj[0], w1 = pj[1], w2 = pj[2], w3 = pj[3];
            u64 xjp[8] = {w0.x, w0.y, w1.x, w1.y, w2.x, w2.y, w3.x, w3.y};

            float kl[8], kh[8];
            u64 p[8], q[8];
            #pragma unroll
            for (int c = 0; c < 8; c++) {
                u64 dp = add2(xjp[c], nxi[c]);
                float dl, dh; upk(dp, dl, dh);
                float al = -dl * dl, ah = -dh * dh;
                asm("ex2.approx.f32 %0, %1;" : "=f"(kl[c]) : "f"(al));
                asm("ex2.approx.f32 %0, %1;" : "=f"(kh[c]) : "f"(ah));
                p[c] = pk(kl[c], kh[c]);
                q[c] = pk(kh[c], kl[c]);
                a_p[c] = add2(a_p[c], p[c]);
            }
            #pragma unroll
            for (int i8 = 0; i8 < 8; i8++) {
                #pragma unroll
                for (int j8 = i8 + 1; j8 < 8; j8++) {
                    tLL[TRI8(i8, j8)] = fma2(p[i8], p[j8], tLL[TRI8(i8, j8)]);
                    tX [TRI8(i8, j8)] = fma2(p[i8], q[j8], tX [TRI8(i8, j8)]);
                }
                tD[i8] = fmaf(kl[i8], kh[i8], tD[i8]);
            }
        }

        // reduce row sums A for this row (canonical feature order)
        #pragma unroll
        for (int c = 0; c < 8; c++) {
            float lo, hi; upk(a_p[c], lo, hi);
            lo = wred(lo); hi = wred(hi);
            if (lane == 0) { s_a[warp * F + c] = lo; s_a[warp * F + c + 8] = hi; }
        }
        __syncthreads();
        if (tid < F) {
            float s = 0.f;
            #pragma unroll
            for (int w = 0; w < 8; w++) s += s_a[w * F + tid];
            g_A[i * F + tid] = s;
        }
        __syncthreads();
    }

    // reduce T partials: warp shuffle -> smem (canonical TRI16 order) -> fp64 atomic
    #pragma unroll
    for (int i8 = 0; i8 < 8; i8++) {
        #pragma unroll
        for (int j8 = i8 + 1; j8 < 8; j8++) {
            float lo, hi;
            upk(tLL[TRI8(i8, j8)], lo, hi);
            lo = wred(lo); hi = wred(hi);
            if (lane == 0) {
                s_t[warp * NPAIR + TRI16(i8, j8)]         = lo;
                s_t[warp * NPAIR + TRI16(i8 + 8, j8 + 8)] = hi;
            }
            upk(tX[TRI8(i8, j8)], lo, hi);
            lo = wred(lo); hi = wred(hi);
            if (lane == 0) {
                s_t[warp * NPAIR + TRI16(i8, j8 + 8)] = lo;   // k_i * k_{8+j}
                s_t[warp * NPAIR + TRI16(j8, i8 + 8)] = hi;   // k_j * k_{8+i}
            }
        }
        float d = wred(tD[i8]);
        if (lane == 0) s_t[warp * NPAIR + TRI16(i8, i8 + 8)] = d;
    }
    __syncthreads();
    for (int e = tid; e < NPAIR; e += 256) {
        double s = 0.0;
        #pragma unroll
        for (int w = 0; w < 8; w++) s += (double)s_t[w * NPAIR + e];
        atomicAdd(&g_T[e], s);
    }
}

// ---------------------------------------------------------------------------
// k3: Dm and S from (A - 1). 32 blocks x 64 rows; smem stage, fp32 partials,
// fp64 atomics. (fp32 partial error ~O(10) abs on Dm ~1e9 -> negligible in h.)
// ---------------------------------------------------------------------------
__global__ void hsic_dm() {
    const int tid = threadIdx.x;
    const int r0 = blockIdx.x * 64;
    __shared__ float sA[64 * F];
    for (int idx = tid; idx < 64 * F; idx += 256)
        sA[idx] = g_A[r0 * F + idx] - 1.0f;
    __syncthreads();
    if (tid < NPAIR) {
        int aa = 0, rem = tid;
        while (rem >= 15 - aa) { rem -= 15 - aa; aa++; }
        int bb = aa + 1 + rem;
        float acc = 0.f;
        #pragma unroll 8
        for (int r = 0; r < 64; r++) acc = fmaf(sA[r * F + aa], sA[r * F + bb], acc);
        atomicAdd(&g_Dm[tid], (double)acc);
    } else if (tid < NPAIR + F) {
        int c = tid - NPAIR;
        float acc = 0.f;
        #pragma unroll 8
        for (int r = 0; r < 64; r++) acc += sA[r * F + c];
        atomicAdd(&g_S[c], (double)acc);
    }
}

// ---------------------------------------------------------------------------
// k4: combine in fp64, sum hsic^2 over strict upper triangle, write fp32.
// ---------------------------------------------------------------------------
__global__ void hsic_final(float* __restrict__ out) {
    __shared__ double sh[128];
    const int tid = threadIdx.x;
    double v = 0.0;
    if (tid < NPAIR) {
        int aa = 0, rem = tid;
        while (rem >= 15 - aa) { rem -= 15 - aa; aa++; }
        int bb = aa + 1 + rem;
        const double n = (double)N;
        double T = g_T[tid] - n;                    // remove diagonal contribution
        double c0 = 1.0 / (n * (n - 3.0));
        double h = c0 * (T + g_S[aa] * g_S[bb] / ((n - 1.0) * (n - 2.0))
                           - (2.0 / (n - 2.0)) * g_Dm[tid]);
        v = h * h;
    }
    sh[tid] = v;
    __syncthreads();
    for (int off = 64; off > 0; off >>= 1) {
        if (tid < off) sh[tid] += sh[tid + off];
        __syncthreads();
    }
    if (tid == 0) out[0] = (float)sh[0];
}

extern "C" void kernel_launch(void* const* d_in, const int* in_sizes, int n_in,
                              void* d_out, int out_size) {
    const float* X = (const float*)d_in[0];
    hsic_stats<<<1, 1024>>>(X);
    hsic_scale<<<(N * F + 255) / 256, 256>>>(X);
    hsic_main<<<N / ROWS_PER_BLOCK, 256>>>();
    hsic_dm<<<N / 64, 256>>>();
    hsic_final<<<1, 128>>>((float*)d_out);
}

// round 3
// speedup vs baseline: 1.5331x; 1.4378x over previous
#include <cuda_runtime.h>
#include <cuda_bf16.h>
#include <math.h>

// HSIC_1855425872455: X [2048,16] fp32 -> scalar fp32
// R3: symmetric (i<j) 64x64 tiling with systolic colA ring; fused stats/scale.

#define N 2048
#define F 16
#define NPAIR 120
#define TILE 64
#define NT (N / TILE)              // 32
#define NBLK (NT * (NT + 1) / 2)   // 528
#define TRI16(a,b) ((a)*15 - (a)*((a)-1)/2 + ((b)-(a)-1))

__device__ float  g_Xs[N * F];
__device__ float  g_A[N * F];
__device__ double g_T[NPAIR];
__device__ double g_Dm[NPAIR];
__device__ double g_S[F];

__device__ __forceinline__ float ex2f(float x) {
    float r; asm("ex2.approx.f32 %0, %1;" : "=f"(r) : "f"(x)); return r;
}
__device__ __forceinline__ float wred(float v) {
    v += __shfl_xor_sync(0xffffffffu, v, 16);
    v += __shfl_xor_sync(0xffffffffu, v, 8);
    v += __shfl_xor_sync(0xffffffffu, v, 4);
    v += __shfl_xor_sync(0xffffffffu, v, 2);
    v += __shfl_xor_sync(0xffffffffu, v, 1);
    return v;
}

// ---------------------------------------------------------------------------
// k1: column stats -> scale; scale X into g_Xs; zero g_A / g_T / g_Dm / g_S.
// 1 block, 1024 threads.
// ---------------------------------------------------------------------------
__global__ void hsic_stats_scale(const float* __restrict__ X) {
    const int tid = threadIdx.x;
    const int col = tid & 15, part = tid >> 4;         // 64 partials per column
    __shared__ float shs[1024], shq[1024];
    __shared__ float s_sc[F];
    float s = 0.f, sq = 0.f;
    for (int r = part; r < N; r += 64) {
        float v = X[r * F + col];
        s += v;
        sq = fmaf(v, v, sq);
    }
    shs[tid] = s; shq[tid] = sq;
    __syncthreads();
    if (tid < F) {
        double ts = 0.0, tq = 0.0;
        #pragma unroll
        for (int p = 0; p < 64; p++) { ts += (double)shs[p * 16 + tid]; tq += (double)shq[p * 16 + tid]; }
        double m1 = ts / (double)N, m2 = tq / (double)N;
        double meanD = 2.0 * (m2 - m1 * m1);
        s_sc[tid] = (float)sqrt(1.4426950408889634 / (2.0 * meanD));
    }
    if (tid < NPAIR) { g_T[tid] = 0.0; g_Dm[tid] = 0.0; }
    if (tid < F) g_S[tid] = 0.0;
    __syncthreads();
    // scale + zero A: 8192 float4s, 8 per thread
    const float4* X4 = (const float4*)X;
    float4* Xs4 = (float4*)g_Xs;
    float4* A4  = (float4*)g_A;
    const float4 z4 = make_float4(0.f, 0.f, 0.f, 0.f);
    for (int q = tid; q < N * F / 4; q += 1024) {
        int c0 = (q & 3) * 4;
        float4 v = X4[q];
        v.x *= s_sc[c0]; v.y *= s_sc[c0 + 1]; v.z *= s_sc[c0 + 2]; v.w *= s_sc[c0 + 3];
        Xs4[q] = v;
        A4[q] = z4;
    }
}

// ---------------------------------------------------------------------------
// k2: symmetric tiled main pass.
// Block = tile (ti, tj), ti<=tj. 8 warps:
//   warp w: ii = I0 + (w>=4)*32 + lane, jj range = [J0 + 16*(w&3), +16)
// Systolic: at step s, lane l handles jj = jj0 + ((l+s)&15). rowA register-
// resident (lane-owned ii); colA is a traveling register accumulator rotated
// by one lane per step within width-16 shuffle segments.
// Off-diagonal tiles: T weight 2, rowA->I rows, colA->J rows.
// Diagonal tiles:     T weight 1, rowA only (colA would double-count).
// Self pairs (i==j, k=1) included; corrected downstream (A-1, T-n).
// ---------------------------------------------------------------------------
__global__ __launch_bounds__(256, 1) void hsic_main() {
    const int tid = threadIdx.x;
    const int w = tid >> 5, l = tid & 31;
    const int lseg = l & 15;

    // decode (ti, tj) from blockIdx
    int ti = 0, rem = blockIdx.x;
    while (rem >= NT - ti) { rem -= NT - ti; ti++; }
    const int tj = ti + rem;
    const int I0 = ti * TILE, J0 = tj * TILE;
    const bool diag = (ti == tj);

    __shared__ float s_xj[TILE * 17];
    __shared__ float s_row[8][32][17];
    __shared__ float s_col[8][16][17];
    __shared__ float s_t[8][NPAIR];

    // stage J tile rows into smem (padded stride 17)
    for (int idx = tid; idx < TILE * F; idx += 256) {
        int r = idx >> 4, c = idx & 15;
        s_xj[r * 17 + c] = g_Xs[(J0 + r) * F + c];
    }

    // per-lane fixed row
    const int iiG = I0 + ((w >> 2) << 5) + l;
    const int jj0 = (w & 3) << 4;
    float xi[F];
    {
        const float4* p = (const float4*)(g_Xs + iiG * F);
        float4 a = p[0], b = p[1], c = p[2], d = p[3];
        xi[0]=a.x; xi[1]=a.y; xi[2]=a.z; xi[3]=a.w;
        xi[4]=b.x; xi[5]=b.y; xi[6]=b.z; xi[7]=b.w;
        xi[8]=c.x; xi[9]=c.y; xi[10]=c.z; xi[11]=c.w;
        xi[12]=d.x; xi[13]=d.y; xi[14]=d.z; xi[15]=d.w;
    }
    __syncthreads();

    float rowA[F], colA[F], t[NPAIR];
    #pragma unroll
    for (int c = 0; c < F; c++) { rowA[c] = 0.f; colA[c] = 0.f; }
    #pragma unroll
    for (int e = 0; e < NPAIR; e++) t[e] = 0.f;

    #pragma unroll 1
    for (int s = 0; s < 16; s++) {
        const int jj = jj0 + ((l + s) & 15);
        const float* xj = s_xj + jj * 17;
        float k[F];
        #pragma unroll
        for (int c = 0; c < F; c++) {
            float d = xi[c] - xj[c];
            k[c] = ex2f(d * -d);
            rowA[c] += k[c];
            colA[c] += k[c];
        }
        #pragma unroll
        for (int a = 0; a < F; a++)
            #pragma unroll
            for (int b = a + 1; b < F; b++)
                t[TRI16(a, b)] = fmaf(k[a], k[b], t[TRI16(a, b)]);
        // rotate colA: lane receives accumulator from lane+1 (width-16 ring)
        const int src = (lseg + 1) & 15;
        #pragma unroll
        for (int c = 0; c < F; c++)
            colA[c] = __shfl_sync(0xffffffffu, colA[c], src, 16);
    }

    // fold the two 16-lane segments: lane lseg holds colA for jj = jj0+lseg
    #pragma unroll
    for (int c = 0; c < F; c++)
        colA[c] += __shfl_xor_sync(0xffffffffu, colA[c], 16);

    // store partials
    #pragma unroll
    for (int c = 0; c < F; c++) s_row[w][l][c] = rowA[c];
    if (l < 16) {
        #pragma unroll
        for (int c = 0; c < F; c++) s_col[w][l][c] = colA[c];
    }
    #pragma unroll
    for (int e = 0; e < NPAIR; e++) t[e] = wred(t[e]);
    if (l == 0) {
        #pragma unroll
        for (int e = 0; e < NPAIR; e++) s_t[w][e] = t[e];
    }
    __syncthreads();

    // A accumulation: 64 rows x 16 c for rowA (and colA if off-diagonal)
    for (int idx = tid; idx < TILE * F; idx += 256) {
        const int ii = idx >> 4, c = idx & 15;
        const int wb = (ii >> 5) * 4, iir = ii & 31;
        float rv = s_row[wb][iir][c] + s_row[wb + 1][iir][c]
                 + s_row[wb + 2][iir][c] + s_row[wb + 3][iir][c];
        atomicAdd(&g_A[(I0 + ii) * F + c], rv);
        if (!diag) {
            const int jw = ii >> 4, jr = ii & 15;
            float cv = s_col[jw][jr][c] + s_col[jw + 4][jr][c];
            atomicAdd(&g_A[(J0 + ii) * F + c], cv);
        }
    }
    // T accumulation
    const double wgt = diag ? 1.0 : 2.0;
    for (int e = tid; e < NPAIR; e += 256) {
        float sT = 0.f;
        #pragma unroll
        for (int ww = 0; ww < 8; ww++) sT += s_t[ww][e];
        atomicAdd(&g_T[e], wgt * (double)sT);
    }
}

// ---------------------------------------------------------------------------
// k3: Dm[a,b] = sum_i (A_a-1)(A_b-1), S_c = sum_i (A_c-1). 64 blocks x 32 rows.
// ---------------------------------------------------------------------------
__global__ void hsic_dm() {
    const int tid = threadIdx.x;
    __shared__ float sA[32 * F];
    for (int idx = tid; idx < 32 * F; idx += 256)
        sA[idx] = g_A[blockIdx.x * 32 * F + idx] - 1.0f;
    __syncthreads();
    if (tid < NPAIR) {
        int aa = 0, rem = tid;
        while (rem >= 15 - aa) { rem -= 15 - aa; aa++; }
        int bb = aa + 1 + rem;
        float acc = 0.f;
        #pragma unroll 8
        for (int r = 0; r < 32; r++) acc = fmaf(sA[r * F + aa], sA[r * F + bb], acc);
        atomicAdd(&g_Dm[tid], (double)acc);
    } else if (tid < NPAIR + F) {
        int c = tid - NPAIR;
        float acc = 0.f;
        #pragma unroll 8
        for (int r = 0; r < 32; r++) acc += sA[r * F + c];
        atomicAdd(&g_S[c], (double)acc);
    }
}

// ---------------------------------------------------------------------------
// k4: combine in fp64, sum hsic^2 over strict upper triangle, write fp32.
// ---------------------------------------------------------------------------
__global__ void hsic_final(float* __restrict__ out) {
    __shared__ double sh[128];
    const int tid = threadIdx.x;
    double v = 0.0;
    if (tid < NPAIR) {
        int aa = 0, rem = tid;
        while (rem >= 15 - aa) { rem -= 15 - aa; aa++; }
        int bb = aa + 1 + rem;
        const double n = (double)N;
        double T = g_T[tid] - n;                    // remove i==j contribution
        double c0 = 1.0 / (n * (n - 3.0));
        double h = c0 * (T + g_S[aa] * g_S[bb] / ((n - 1.0) * (n - 2.0))
                           - (2.0 / (n - 2.0)) * g_Dm[tid]);
        v = h * h;
    }
    sh[tid] = v;
    __syncthreads();
    for (int off = 64; off > 0; off >>= 1) {
        if (tid < off) sh[tid] += sh[tid + off];
        __syncthreads();
    }
    if (tid == 0) out[0] = (float)sh[0];
}

extern "C" void kernel_launch(void* const* d_in, const int* in_sizes, int n_in,
                              void* d_out, int out_size) {
    const float* X = (const float*)d_in[0];
    hsic_stats_scale<<<1, 1024>>>(X);
    hsic_main<<<NBLK, 256>>>();
    hsic_dm<<<N / 32, 256>>>();
    hsic_final<<<1, 128>>>((float*)d_out);
}